// round 7
// baseline (speedup 1.0000x reference)
#include <cuda.h>
#include <cuda_runtime.h>
#include <cuda_bf16.h>
#include <cstdint>

// loss = mean_{i!=j} (cos(q_i,q_j) - cos(k_i,k_j))^2
// Sq_ij - Sk_ij = [u_i,v_i].[u_j,-v_j]  =>  C = P @ P^T with b_negate on the
// v-half K-chunks. tcgen05 path: 2-CTA clusters (512x256 super-tile) with TMA
// multicast sharing the B tile; single-thread pipeline (no block syncs in the
// mainloop). Epilogue square-sums the strict upper triangle (x2); finalize
// fused into the last CTA via arrival counter.

#if defined(__CUDA_ARCH_FEAT_SM100_ALL) || defined(__CUDA_ARCH_FEAT_SM103_ALL) || \
    (defined(__CUDA_ARCH_SPECIFIC__) && (__CUDA_ARCH_SPECIFIC__ >= 1000) && (__CUDA_ARCH_SPECIFIC__ < 1100))
#define HAS_TC 1
#else
#define HAS_TC 0
#endif

#define NROWS 4096
#define DDIM  1024
#define KTOT  2048

// ---- tcgen05 tile config ----
#define BM 256
#define BN 256
#define KC 64                       // bf16 elems per chunk (128 B per row)
#define NCHUNK (KTOT / KC)          // 32
#define NEGCHUNK (DDIM / KC)        // 16
#define NSTAGE 3
#define NSUPER 72                   // I in 0..7 (512-row supers), J >= 2I
#define NTILES_TC (2 * NSUPER)      // 144 CTAs

#define A_STAGE_BYTES (BM * 128)    // 32768
#define B_STAGE_BYTES (BN * 128)    // 32768
#define STAGE_BYTES   (A_STAGE_BYTES + B_STAGE_BYTES)   // 65536
#define SMEM_HDR      1024
#define SMEM_DYN      (1024 + SMEM_HDR + NSTAGE * STAGE_BYTES)

// idesc: F32 acc, BF16 a/b, N=256, M=128, K-major; bit14 = b_negate
#define MMA_IDESC ((1u<<4) | (1u<<7) | (1u<<10) | ((256u/8u)<<17) | ((128u/16u)<<24))
#define MMA_IDESC_NEGB (MMA_IDESC | (1u<<14))

// ---- FFMA fallback tile config ----
#define FBM 128
#define FBK 16
#define LDSS 132
#define NTILES_FF 528

__device__ __nv_bfloat16 g_P[(size_t)NROWS * KTOT];  // [u, v] (unit rows)
__device__ double g_acc;
__device__ unsigned int g_count;

// ---------------------------------------------------------------------------
// Arch-neutral helpers
// ---------------------------------------------------------------------------
__device__ __forceinline__ uint32_t smem_u32(const void* p) {
    uint32_t a;
    asm("{ .reg .u64 t; cvta.to.shared.u64 t, %1; cvt.u32.u64 %0, t; }"
        : "=r"(a) : "l"(p));
    return a;
}

#define MBAR_INIT(a, n) \
    asm volatile("mbarrier.init.shared.b64 [%0], %1;" :: "r"(a), "r"(n) : "memory")
#define MBAR_INVAL(a) \
    asm volatile("mbarrier.inval.shared.b64 [%0];" :: "r"(a) : "memory")
#define MBAR_EXPECT_TX(a, tx) \
    asm volatile("mbarrier.arrive.expect_tx.shared.b64 _, [%0], %1;" \
                 :: "r"(a), "r"(tx) : "memory")
#define MBAR_WAIT(a, p) do { \
    uint32_t _m = (a); uint32_t _p = (p); uint32_t _d; \
    asm volatile("{\n\t.reg .pred q;\n\t" \
        "mbarrier.try_wait.parity.acquire.cta.shared::cta.b64 q, [%1], %2;\n\t" \
        "selp.b32 %0, 1, 0, q;\n\t}" : "=r"(_d) : "r"(_m), "r"(_p) : "memory"); \
    if (!_d) { \
        asm volatile("{\n\t.reg .pred Q1;\n\tWL_%=:\n\t" \
            "mbarrier.try_wait.parity.acquire.cta.shared::cta.b64 Q1, [%0], %1, 0x989680;\n\t" \
            "@Q1 bra.uni WD_%=;\n\tbra.uni WL_%=;\n\tWD_%=:\n\t}" \
            :: "r"(_m), "r"(_p) : "memory"); \
    } } while (0)

// finalize fused into last CTA
__device__ __forceinline__ void block_finalize(int tid, float* out, unsigned ntiles) {
    if (tid == 0) {
        __threadfence();
        unsigned old = atomicAdd(&g_count, 1u);
        if (old == ntiles - 1) {
            double s = atomicAdd(&g_acc, 0.0);
            out[0] = (float)(s / ((double)NROWS * (double)(NROWS - 1)));
            g_acc = 0.0;
            g_count = 0u;
            __threadfence();
        }
    }
}

// ---------------------------------------------------------------------------
// Kernel 1: normalize rows -> bf16 P=[u,v]. 1 row/block, fully coalesced.
// ---------------------------------------------------------------------------
__global__ __launch_bounds__(256) void norm_kernel(const float* __restrict__ fq,
                                                   const float* __restrict__ fk) {
    int b = blockIdx.x;
    int row = b & (NROWS - 1);
    int which = b >> 12;
    const float* src = (which ? fk : fq) + (size_t)row * DDIM;

    int t = threadIdx.x;
    float4 v = reinterpret_cast<const float4*>(src)[t];
    float ss = v.x * v.x + v.y * v.y + v.z * v.z + v.w * v.w;
#pragma unroll
    for (int o = 16; o; o >>= 1) ss += __shfl_xor_sync(0xffffffffu, ss, o);

    __shared__ float warp_s[8];
    __shared__ float s_inv;
    if ((t & 31) == 0) warp_s[t >> 5] = ss;
    __syncthreads();
    if (t == 0) {
        float tot = 0.f;
#pragma unroll
        for (int w = 0; w < 8; w++) tot += warp_s[w];
        s_inv = rsqrtf(tot);
        if (b == 0) g_acc = 0.0;
    }
    __syncthreads();
    float inv = s_inv;

    __nv_bfloat162 p0 = __floats2bfloat162_rn(v.x * inv, v.y * inv);
    __nv_bfloat162 p1 = __floats2bfloat162_rn(v.z * inv, v.w * inv);
    size_t base = (size_t)row * KTOT + (size_t)which * DDIM + (size_t)t * 4;
    *reinterpret_cast<__nv_bfloat162*>(&g_P[base])     = p0;
    *reinterpret_cast<__nv_bfloat162*>(&g_P[base + 2]) = p1;
}

// ---------------------------------------------------------------------------
// tcgen05-only helpers
// ---------------------------------------------------------------------------
#if HAS_TC
#define TC_ALLOC(sa, n) \
    asm volatile("tcgen05.alloc.cta_group::1.sync.aligned.shared::cta.b32 [%0], %1;" \
                 :: "r"(sa), "r"(n) : "memory")
#define TC_RELINQ() \
    asm volatile("tcgen05.relinquish_alloc_permit.cta_group::1.sync.aligned;")
#define TC_DEALLOC(t, n) \
    asm volatile("tcgen05.dealloc.cta_group::1.sync.aligned.b32 %0, %1;" :: "r"(t), "r"(n))
#define TC_COMMIT(mb) \
    asm volatile("tcgen05.commit.cta_group::1.mbarrier::arrive::one.shared::cluster.b64 [%0];" \
                 :: "r"(mb) : "memory")
#define TC_FENCE_AFTER() asm volatile("tcgen05.fence::after_thread_sync;" ::: "memory")
#define TC_FENCE_BEFORE() asm volatile("tcgen05.fence::before_thread_sync;" ::: "memory")
#define TC_WAIT_LD() asm volatile("tcgen05.wait::ld.sync.aligned;" ::: "memory")

#define CLUSTER_ARRIVE() asm volatile("barrier.cluster.arrive.aligned;" ::: "memory")
#define CLUSTER_WAIT()   asm volatile("barrier.cluster.wait.aligned;" ::: "memory")

__device__ __forceinline__ uint32_t cl_rank() {
    uint32_t r;
    asm("mov.u32 %0, %%cluster_ctarank;" : "=r"(r));
    return r;
}

// remote arrive at same smem offset in cluster CTA `trank`
#define MBAR_ARRIVE_CL(addr, trank) \
    asm volatile("{ .reg .b32 ra;\n\t" \
        "mapa.shared::cluster.u32 ra, %0, %1;\n\t" \
        "mbarrier.arrive.shared::cluster.b64 _, [ra];\n\t}" \
        :: "r"(addr), "r"(trank) : "memory")

// 2D TMA multicast load (cluster-shared smem dest, tx to each dest's barrier)
#define TMA2D_MC(smem, tmap_p, x, y, mbar, mask) \
    asm volatile( \
        "cp.async.bulk.tensor.2d.shared::cluster.global.tile.mbarrier::complete_tx::bytes.multicast::cluster " \
        "[%0], [%1, {%2, %3}], [%4], %5;" \
        :: "r"(smem), "l"(tmap_p), "r"(x), "r"(y), "r"(mbar), "h"(mask) : "memory")

// SW128 K-major SMEM descriptor (LBO=1, SBO=64, version=1)
__device__ __forceinline__ uint64_t make_desc(uint32_t addr) {
    return (uint64_t(2) << 61) | (uint64_t(1) << 46) | (uint64_t(64) << 32)
         | (uint64_t(1) << 16) | ((uint64_t)(addr >> 4) & 0x3FFF);
}

__device__ __forceinline__ void mma_f16_ss(uint32_t d, uint64_t a, uint64_t b,
                                           uint32_t idesc, uint32_t enable) {
    asm volatile(
        "{\n\t.reg .pred p;\n\tsetp.ne.u32 p, %5, 0;\n\t"
        "tcgen05.mma.cta_group::1.kind::f16 [%0], %1, %2, %3, {%4,%4,%4,%4}, p;\n\t}"
        :: "r"(d), "l"(a), "l"(b), "r"(idesc), "r"(0u), "r"(enable) : "memory");
}

#define TC_LD_X32(r, ta) \
    asm volatile( \
        "tcgen05.ld.sync.aligned.32x32b.x32.b32 " \
        "{%0,%1,%2,%3,%4,%5,%6,%7,%8,%9,%10,%11,%12,%13,%14,%15," \
        "%16,%17,%18,%19,%20,%21,%22,%23,%24,%25,%26,%27,%28,%29,%30,%31}, [%32];" \
        : "=r"((r)[0]),"=r"((r)[1]),"=r"((r)[2]),"=r"((r)[3]), \
          "=r"((r)[4]),"=r"((r)[5]),"=r"((r)[6]),"=r"((r)[7]), \
          "=r"((r)[8]),"=r"((r)[9]),"=r"((r)[10]),"=r"((r)[11]), \
          "=r"((r)[12]),"=r"((r)[13]),"=r"((r)[14]),"=r"((r)[15]), \
          "=r"((r)[16]),"=r"((r)[17]),"=r"((r)[18]),"=r"((r)[19]), \
          "=r"((r)[20]),"=r"((r)[21]),"=r"((r)[22]),"=r"((r)[23]), \
          "=r"((r)[24]),"=r"((r)[25]),"=r"((r)[26]),"=r"((r)[27]), \
          "=r"((r)[28]),"=r"((r)[29]),"=r"((r)[30]),"=r"((r)[31]) \
        : "r"(ta))
#endif  // HAS_TC

// ---------------------------------------------------------------------------
// Kernel 2a: cluster-2 TMA-multicast tcgen05 GEMM + fused epilogue/finalize
// Super-tile: 512 M-rows (2 CTAs, ti = 2I+rank) x 256 N-cols (tj = J, B shared)
// ---------------------------------------------------------------------------
__global__ __launch_bounds__(256, 1) __cluster_dims__(2, 1, 1)
void gemm_tc(float* out, const __grid_constant__ CUtensorMap tmap) {
#if HAS_TC
    extern __shared__ __align__(16) char smem[];
    uint32_t sb_raw = smem_u32(smem);
    uint32_t smem_base = (sb_raw + 1023u) & ~1023u;
    int tid = threadIdx.x;
    int wid = tid >> 5;
    int lid = tid & 31;
    uint32_t rank = cl_rank();

    // super id -> (I, J): I in 0..7, J in 2I..15
    int t = blockIdx.x >> 1;
    int I = 0;
    while (t >= (16 - 2 * I)) { t -= (16 - 2 * I); I++; }
    int J = 2 * I + t;
    int ti = 2 * I + (int)rank;       // M 256-block (0..15)
    int tj = J;                       // N 256-block (0..15)

    // header: [0] tmem ptr; full[3]@8; empty[3]@32; mma[3]@56; final@80
    uint32_t full0 = smem_base + 8, empty0 = smem_base + 32;
    uint32_t mma0 = smem_base + 56, finmb = smem_base + 80;

    if (wid == 0) TC_ALLOC(smem_base, 512);
    if (tid == 0) {
#pragma unroll
        for (int s = 0; s < NSTAGE; s++) {
            MBAR_INIT(full0 + 8 * s, 1);
            MBAR_INIT(empty0 + 8 * s, 2);   // both ranks arrive (B consumers)
            MBAR_INIT(mma0 + 8 * s, 1);
        }
        MBAR_INIT(finmb, 1);
    }
    __syncthreads();
    uint32_t tmem;
    asm volatile("ld.shared.b32 %0, [%1];" : "=r"(tmem) : "r"(smem_base));

    // peer barriers must be visible before multicast TMA targets them
    CLUSTER_ARRIVE();
    CLUSTER_WAIT();

    uint32_t stA[NSTAGE], stB[NSTAGE];
#pragma unroll
    for (int s = 0; s < NSTAGE; s++) {
        stA[s] = smem_base + SMEM_HDR + s * STAGE_BYTES;
        stB[s] = stA[s] + A_STAGE_BYTES;
    }

    const CUtensorMap* tm = &tmap;
    uint16_t maskA = (uint16_t)(1u << rank);   // self only
    uint16_t maskB = 0x3;                      // both CTAs
    int rowA = ti * BM;
    int rowB = tj * BN;
    bool issueB = (rank == 0);

    if (tid == 0) {
        // prologue: chunks 0..NSTAGE-2
#pragma unroll
        for (int pc = 0; pc < NSTAGE - 1; pc++) {
            MBAR_EXPECT_TX(full0 + 8 * pc, STAGE_BYTES);
            TMA2D_MC(stA[pc], tm, pc * KC, rowA, full0 + 8 * pc, maskA);
            if (issueB) TMA2D_MC(stB[pc], tm, pc * KC, rowB, full0 + 8 * pc, maskB);
        }

        for (int c = 0; c < NCHUNK; c++) {
            int st = c % NSTAGE;
            MBAR_WAIT(full0 + 8 * st, (c / NSTAGE) & 1);

            uint64_t ad  = make_desc(stA[st]);
            uint64_t ad2 = make_desc(stA[st] + 16384);
            uint64_t bd  = make_desc(stB[st]);
            uint32_t idesc = (c >= NEGCHUNK) ? MMA_IDESC_NEGB : MMA_IDESC;
#pragma unroll
            for (int k = 0; k < 4; k++) {
                uint32_t e = (c > 0 || k > 0) ? 1u : 0u;
                mma_f16_ss(tmem,       ad  + 2 * k, bd + 2 * k, idesc, e);
                mma_f16_ss(tmem + 256, ad2 + 2 * k, bd + 2 * k, idesc, e);
            }
            if (c == NCHUNK - 1) TC_COMMIT(finmb);
            else                 TC_COMMIT(mma0 + 8 * st);

            int pre = c + NSTAGE - 1;
            if (pre < NCHUNK) {
                int sp = pre % NSTAGE;
                if (pre >= NSTAGE) {
                    // local MMA on that stage (chunk pre-3) must be complete
                    MBAR_WAIT(mma0 + 8 * sp, ((pre / NSTAGE) - 1) & 1);
                    MBAR_ARRIVE_CL(empty0 + 8 * sp, 0u);   // B-consumer ack
                }
                MBAR_EXPECT_TX(full0 + 8 * sp, STAGE_BYTES);
                if (issueB && pre >= NSTAGE)
                    MBAR_WAIT(empty0 + 8 * sp, ((pre / NSTAGE) - 1) & 1);
                TMA2D_MC(stA[sp], tm, pre * KC, rowA, full0 + 8 * sp, maskA);
                if (issueB) TMA2D_MC(stB[sp], tm, pre * KC, rowB, full0 + 8 * sp, maskB);
            }
        }
    }

    // all threads: wait for the one-shot final MMA barrier
    MBAR_WAIT(finmb, 0);
    TC_FENCE_AFTER();

    // epilogue: warps 0-3 -> rows 0..127, warps 4-7 -> rows 128..255
    __shared__ float red[8];
    {
        int half = wid >> 2;
        uint32_t dbase = tmem + half * 256;
        int i = ti * BM + half * 128 + (wid & 3) * 32 + lid;
        float lsum = 0.f;
#pragma unroll
        for (int cb = 0; cb < 8; cb++) {
            uint32_t r[32];
            TC_LD_X32(r, dbase + cb * 32);
            TC_WAIT_LD();
            int jb = tj * BN + cb * 32;
#pragma unroll
            for (int cc = 0; cc < 32; cc++) {
                if (jb + cc > i) {
                    float f = __uint_as_float(r[cc]);
                    lsum += f * f;
                }
            }
        }
        lsum *= 2.f;
#pragma unroll
        for (int o = 16; o; o >>= 1) lsum += __shfl_xor_sync(0xffffffffu, lsum, o);
        if (lid == 0) red[wid] = lsum;
    }
    TC_FENCE_BEFORE();
    __syncthreads();
    if (tid == 0) {
        double s = 0.0;
#pragma unroll
        for (int w = 0; w < 8; w++) s += (double)red[w];
        atomicAdd(&g_acc, s);
#pragma unroll
        for (int st = 0; st < NSTAGE; st++) {
            MBAR_INVAL(full0 + 8 * st);
            MBAR_INVAL(empty0 + 8 * st);
            MBAR_INVAL(mma0 + 8 * st);
        }
        MBAR_INVAL(finmb);
    }
    __syncthreads();
    if (wid == 0) {
        TC_RELINQ();
        TC_DEALLOC(tmem, 512);
    }
    // no CTA may exit while peer multicast into its smem could be in flight
    CLUSTER_ARRIVE();
    CLUSTER_WAIT();
    block_finalize(tid, out, NTILES_TC);
#endif  // HAS_TC
}

// ---------------------------------------------------------------------------
// FFMA2 helpers + fallback GEMM (base-target builds only)
// ---------------------------------------------------------------------------
__device__ __forceinline__ unsigned long long pack_dup(float a) {
    unsigned long long r;
    asm("mov.b64 %0, {%1, %1};" : "=l"(r) : "f"(a));
    return r;
}
__device__ __forceinline__ void ffma2(unsigned long long& d,
                                      unsigned long long a,
                                      unsigned long long b) {
    asm("fma.rn.f32x2 %0, %1, %2, %0;" : "+l"(d) : "l"(a), "l"(b));
}

__global__ __launch_bounds__(256) void gemm_ffma(float* out) {
#if !HAS_TC
    int b = blockIdx.x;
    int ti = 0;
    while (b >= (32 - ti)) { b -= (32 - ti); ti++; }
    int tj = ti + b;

    __shared__ __align__(16) float As[FBK][LDSS];
    __shared__ __align__(16) float Bs[FBK][LDSS];
    __shared__ float red[8];

    int tid = threadIdx.x;
    int tx = tid & 15;
    int ty = tid >> 4;

    const __nv_bfloat16* Abase = g_P + (size_t)ti * FBM * KTOT;
    const __nv_bfloat16* Bbase = g_P + (size_t)tj * FBM * KTOT;

    int l_row = tid >> 1;
    int l_k8  = (tid & 1) * 8;

    unsigned long long acc[8][4];
#pragma unroll
    for (int r = 0; r < 8; r++)
#pragma unroll
        for (int c = 0; c < 4; c++) acc[r][c] = 0ull;

    uint4 ra = *reinterpret_cast<const uint4*>(
        reinterpret_cast<const char*>(Abase) + (size_t)(l_row * KTOT + l_k8) * 2);
    uint4 rb = *reinterpret_cast<const uint4*>(
        reinterpret_cast<const char*>(Bbase) + (size_t)(l_row * KTOT + l_k8) * 2);

    for (int kb = 0; kb < KTOT; kb += FBK) {
        float sgn = (kb >= DDIM) ? -1.0f : 1.0f;
        union { uint4 u; __nv_bfloat162 h[4]; } wa, wb;
        wa.u = ra; wb.u = rb;
#pragma unroll
        for (int j = 0; j < 4; j++) {
            float2 fa = __bfloat1622float2(wa.h[j]);
            float2 fb = __bfloat1622float2(wb.h[j]);
            As[l_k8 + 2 * j][l_row]     = fa.x;
            As[l_k8 + 2 * j + 1][l_row] = fa.y;
            Bs[l_k8 + 2 * j][l_row]     = sgn * fb.x;
            Bs[l_k8 + 2 * j + 1][l_row] = sgn * fb.y;
        }
        __syncthreads();

        if (kb + FBK < KTOT) {
            int kn = kb + FBK;
            ra = *reinterpret_cast<const uint4*>(
                reinterpret_cast<const char*>(Abase) + (size_t)(l_row * KTOT + kn + l_k8) * 2);
            rb = *reinterpret_cast<const uint4*>(
                reinterpret_cast<const char*>(Bbase) + (size_t)(l_row * KTOT + kn + l_k8) * 2);
        }

#pragma unroll
        for (int kk = 0; kk < FBK; kk++) {
            float a[8];
            *reinterpret_cast<float4*>(&a[0]) =
                *reinterpret_cast<const float4*>(&As[kk][ty * 8]);
            *reinterpret_cast<float4*>(&a[4]) =
                *reinterpret_cast<const float4*>(&As[kk][ty * 8 + 4]);
            union { float4 v[2]; unsigned long long u[4]; } bu;
            bu.v[0] = *reinterpret_cast<const float4*>(&Bs[kk][tx * 8]);
            bu.v[1] = *reinterpret_cast<const float4*>(&Bs[kk][tx * 8 + 4]);
#pragma unroll
            for (int r = 0; r < 8; r++) {
                unsigned long long aa = pack_dup(a[r]);
#pragma unroll
                for (int c = 0; c < 4; c++) ffma2(acc[r][c], aa, bu.u[c]);
            }
        }
        __syncthreads();
    }

    int gi0 = ti * FBM + ty * 8;
    int gj0 = tj * FBM + tx * 8;
    float lsum = 0.f;
#pragma unroll
    for (int r = 0; r < 8; r++) {
        int i = gi0 + r;
#pragma unroll
        for (int c = 0; c < 4; c++) {
            union { unsigned long long u; float f[2]; } w;
            w.u = acc[r][c];
            int j0 = gj0 + 2 * c;
            if (j0 > i)     lsum += w.f[0] * w.f[0];
            if (j0 + 1 > i) lsum += w.f[1] * w.f[1];
        }
    }
    lsum *= 2.f;

#pragma unroll
    for (int o = 16; o; o >>= 1) lsum += __shfl_xor_sync(0xffffffffu, lsum, o);
    if ((tid & 31) == 0) red[tid >> 5] = lsum;
    __syncthreads();
    if (tid == 0) {
        double s = 0.0;
#pragma unroll
        for (int w = 0; w < 8; w++) s += (double)red[w];
        atomicAdd(&g_acc, s);
    }
    __syncthreads();
    block_finalize(tid, out, NTILES_FF);
#endif  // !HAS_TC
}

// ---------------------------------------------------------------------------
// Host
// ---------------------------------------------------------------------------
typedef CUresult (*PFN_tmapEncode)(
    CUtensorMap*, CUtensorMapDataType, cuuint32_t, void*,
    const cuuint64_t*, const cuuint64_t*, const cuuint32_t*, const cuuint32_t*,
    CUtensorMapInterleave, CUtensorMapSwizzle, CUtensorMapL2promotion,
    CUtensorMapFloatOOBfill);

static CUtensorMap s_tmap;   // persistent; snapshot into graph at launch

extern "C" void kernel_launch(void* const* d_in, const int* in_sizes, int n_in,
                              void* d_out, int out_size) {
    const float* fq = (const float*)d_in[0];
    const float* fk = (const float*)d_in[1];
    (void)in_sizes; (void)n_in; (void)out_size;

    cudaFuncSetAttribute(gemm_tc,
                         cudaFuncAttributeMaxDynamicSharedMemorySize, SMEM_DYN);

    // build TMA descriptor for g_P (bf16 [NROWS rows x KTOT cols], box 64x256)
    void* pbase = nullptr;
    cudaGetSymbolAddress(&pbase, g_P);
    void* fn = nullptr;
    cudaDriverEntryPointQueryResult qr;
    cudaGetDriverEntryPointByVersion("cuTensorMapEncodeTiled", &fn, 12000,
                                     cudaEnableDefault, &qr);
    if (fn && pbase) {
        cuuint64_t dims[2]    = {(cuuint64_t)KTOT, (cuuint64_t)NROWS};
        cuuint64_t strides[1] = {(cuuint64_t)KTOT * 2};
        cuuint32_t box[2]     = {KC, 256};
        cuuint32_t es[2]      = {1, 1};
        ((PFN_tmapEncode)fn)(&s_tmap, CU_TENSOR_MAP_DATA_TYPE_BFLOAT16, 2, pbase,
                             dims, strides, box, es,
                             CU_TENSOR_MAP_INTERLEAVE_NONE,
                             CU_TENSOR_MAP_SWIZZLE_128B,
                             CU_TENSOR_MAP_L2_PROMOTION_L2_128B,
                             CU_TENSOR_MAP_FLOAT_OOB_FILL_NONE);
    }

    norm_kernel<<<2 * NROWS, 256>>>(fq, fk);
    gemm_tc<<<NTILES_TC, 256, SMEM_DYN>>>((float*)d_out, s_tmap);
    gemm_ffma<<<NTILES_FF, 256>>>((float*)d_out);
}

// round 8
// speedup vs baseline: 1.1453x; 1.1453x over previous
#include <cuda.h>
#include <cuda_runtime.h>
#include <cuda_bf16.h>
#include <cstdint>

// loss = mean_{i!=j} (cos(q_i,q_j) - cos(k_i,k_j))^2
// Sq_ij - Sk_ij = [u_i,v_i].[u_j,-v_j]  =>  C = P @ P^T with b_negate on the
// v-half K-chunks (idesc bit 14). tcgen05 path: per-CTA TMA single-thread
// pipeline (no block syncs, no clusters). Epilogue square-sums the strict
// upper triangle (x2); finalize fused into the last CTA via arrival counter.

#if defined(__CUDA_ARCH_FEAT_SM100_ALL) || defined(__CUDA_ARCH_FEAT_SM103_ALL) || \
    (defined(__CUDA_ARCH_SPECIFIC__) && (__CUDA_ARCH_SPECIFIC__ >= 1000) && (__CUDA_ARCH_SPECIFIC__ < 1100))
#define HAS_TC 1
#else
#define HAS_TC 0
#endif

#define NROWS 4096
#define DDIM  1024
#define KTOT  2048

// ---- tcgen05 tile config: 256x256 tile per CTA (2 x M128/N256 MMA) ----
#define BM 256
#define BN 256
#define KC 64                       // bf16 elems per chunk (128 B per row)
#define NCHUNK (KTOT / KC)          // 32
#define NEGCHUNK (DDIM / KC)        // 16
#define NSTAGE 3
#define NT  (NROWS / 256)           // 16
#define NTILES_TC 136               // triangle tj >= ti of 16x16

#define A_STAGE_BYTES (BM * 128)    // 32768
#define B_STAGE_BYTES (BN * 128)    // 32768
#define STAGE_BYTES   (A_STAGE_BYTES + B_STAGE_BYTES)   // 65536
#define SMEM_HDR      1024
#define SMEM_DYN      (1024 + SMEM_HDR + NSTAGE * STAGE_BYTES)

// idesc: F32 acc, BF16 a/b, N=256, M=128, K-major; bit14 = b_negate
#define MMA_IDESC ((1u<<4) | (1u<<7) | (1u<<10) | ((256u/8u)<<17) | ((128u/16u)<<24))
#define MMA_IDESC_NEGB (MMA_IDESC | (1u<<14))

// ---- FFMA fallback tile config ----
#define FBM 128
#define FBK 16
#define LDSS 132
#define NTILES_FF 528

__device__ __nv_bfloat16 g_P[(size_t)NROWS * KTOT];  // [u, v] (unit rows)
__device__ double g_acc;
__device__ unsigned int g_count;

// ---------------------------------------------------------------------------
// Arch-neutral helpers
// ---------------------------------------------------------------------------
__device__ __forceinline__ uint32_t smem_u32(const void* p) {
    uint32_t a;
    asm("{ .reg .u64 t; cvta.to.shared.u64 t, %1; cvt.u32.u64 %0, t; }"
        : "=r"(a) : "l"(p));
    return a;
}

#define MBAR_INIT(a, n) \
    asm volatile("mbarrier.init.shared.b64 [%0], %1;" :: "r"(a), "r"(n) : "memory")
#define MBAR_INVAL(a) \
    asm volatile("mbarrier.inval.shared.b64 [%0];" :: "r"(a) : "memory")
#define MBAR_EXPECT_TX(a, tx) \
    asm volatile("mbarrier.arrive.expect_tx.shared.b64 _, [%0], %1;" \
                 :: "r"(a), "r"(tx) : "memory")
#define MBAR_WAIT(a, p) do { \
    uint32_t _m = (a); uint32_t _p = (p); uint32_t _d; \
    asm volatile("{\n\t.reg .pred q;\n\t" \
        "mbarrier.try_wait.parity.acquire.cta.shared::cta.b64 q, [%1], %2;\n\t" \
        "selp.b32 %0, 1, 0, q;\n\t}" : "=r"(_d) : "r"(_m), "r"(_p) : "memory"); \
    if (!_d) { \
        asm volatile("{\n\t.reg .pred Q1;\n\tWL_%=:\n\t" \
            "mbarrier.try_wait.parity.acquire.cta.shared::cta.b64 Q1, [%0], %1, 0x989680;\n\t" \
            "@Q1 bra.uni WD_%=;\n\tbra.uni WL_%=;\n\tWD_%=:\n\t}" \
            :: "r"(_m), "r"(_p) : "memory"); \
    } } while (0)

// finalize fused into last CTA
__device__ __forceinline__ void block_finalize(int tid, float* out, unsigned ntiles) {
    if (tid == 0) {
        __threadfence();
        unsigned old = atomicAdd(&g_count, 1u);
        if (old == ntiles - 1) {
            double s = atomicAdd(&g_acc, 0.0);
            out[0] = (float)(s / ((double)NROWS * (double)(NROWS - 1)));
            g_acc = 0.0;
            g_count = 0u;
            __threadfence();
        }
    }
}

// ---------------------------------------------------------------------------
// Kernel 1: normalize rows -> bf16 P=[u,v].
// 4 rows/block; thread t holds float4 #t of each of the 4 rows (4 independent
// fully-coalesced LDG.128 -> MLP=4). One 8B packed store per row per thread.
// ---------------------------------------------------------------------------
__global__ __launch_bounds__(256) void norm_kernel(const float* __restrict__ fq,
                                                   const float* __restrict__ fk) {
    int t = threadIdx.x;
    int slot0 = 4 * blockIdx.x;       // 4 consecutive slots, same q/k half
    int which = slot0 >> 12;          // 0 = q, 1 = k (4096 % 4 == 0: no mix)
    const float* srcm = (which ? fk : fq);

    float4 v[4];
#pragma unroll
    for (int r = 0; r < 4; r++) {
        int row = (slot0 + r) & (NROWS - 1);
        v[r] = reinterpret_cast<const float4*>(srcm + (size_t)row * DDIM)[t];
    }

    float ss[4];
#pragma unroll
    for (int r = 0; r < 4; r++) {
        ss[r] = v[r].x * v[r].x + v[r].y * v[r].y
              + v[r].z * v[r].z + v[r].w * v[r].w;
#pragma unroll
        for (int o = 16; o; o >>= 1)
            ss[r] += __shfl_xor_sync(0xffffffffu, ss[r], o);
    }

    __shared__ float warp_s[8][4];
    __shared__ float s_inv[4];
    if ((t & 31) == 0) {
#pragma unroll
        for (int r = 0; r < 4; r++) warp_s[t >> 5][r] = ss[r];
    }
    __syncthreads();
    if (t < 4) {
        float tot = 0.f;
#pragma unroll
        for (int w = 0; w < 8; w++) tot += warp_s[w][t];
        s_inv[t] = rsqrtf(tot);
        if (blockIdx.x == 0 && t == 0) g_acc = 0.0;
    }
    __syncthreads();

#pragma unroll
    for (int r = 0; r < 4; r++) {
        int row = (slot0 + r) & (NROWS - 1);
        float inv = s_inv[r];
        union { uint2 u; __nv_bfloat162 b[2]; } w;
        w.b[0] = __floats2bfloat162_rn(v[r].x * inv, v[r].y * inv);
        w.b[1] = __floats2bfloat162_rn(v[r].z * inv, v[r].w * inv);
        size_t base = (size_t)row * KTOT + (size_t)which * DDIM + (size_t)t * 4;
        *reinterpret_cast<uint2*>(&g_P[base]) = w.u;
    }
}

// ---------------------------------------------------------------------------
// tcgen05-only helpers
// ---------------------------------------------------------------------------
#if HAS_TC
#define TC_ALLOC(sa, n) \
    asm volatile("tcgen05.alloc.cta_group::1.sync.aligned.shared::cta.b32 [%0], %1;" \
                 :: "r"(sa), "r"(n) : "memory")
#define TC_RELINQ() \
    asm volatile("tcgen05.relinquish_alloc_permit.cta_group::1.sync.aligned;")
#define TC_DEALLOC(t, n) \
    asm volatile("tcgen05.dealloc.cta_group::1.sync.aligned.b32 %0, %1;" :: "r"(t), "r"(n))
#define TC_COMMIT(mb) \
    asm volatile("tcgen05.commit.cta_group::1.mbarrier::arrive::one.shared::cluster.b64 [%0];" \
                 :: "r"(mb) : "memory")
#define TC_FENCE_AFTER() asm volatile("tcgen05.fence::after_thread_sync;" ::: "memory")
#define TC_FENCE_BEFORE() asm volatile("tcgen05.fence::before_thread_sync;" ::: "memory")
#define TC_WAIT_LD() asm volatile("tcgen05.wait::ld.sync.aligned;" ::: "memory")

// 2D TMA load into this CTA's smem
#define TMA2D(smem, tmap_p, x, y, mbar) \
    asm volatile( \
        "cp.async.bulk.tensor.2d.shared::cta.global.tile.mbarrier::complete_tx::bytes " \
        "[%0], [%1, {%2, %3}], [%4];" \
        :: "r"(smem), "l"(tmap_p), "r"(x), "r"(y), "r"(mbar) : "memory")

// SW128 K-major SMEM descriptor (LBO=1, SBO=64, version=1)
__device__ __forceinline__ uint64_t make_desc(uint32_t addr) {
    return (uint64_t(2) << 61) | (uint64_t(1) << 46) | (uint64_t(64) << 32)
         | (uint64_t(1) << 16) | ((uint64_t)(addr >> 4) & 0x3FFF);
}

__device__ __forceinline__ void mma_f16_ss(uint32_t d, uint64_t a, uint64_t b,
                                           uint32_t idesc, uint32_t enable) {
    asm volatile(
        "{\n\t.reg .pred p;\n\tsetp.ne.u32 p, %5, 0;\n\t"
        "tcgen05.mma.cta_group::1.kind::f16 [%0], %1, %2, %3, {%4,%4,%4,%4}, p;\n\t}"
        :: "r"(d), "l"(a), "l"(b), "r"(idesc), "r"(0u), "r"(enable) : "memory");
}

#define TC_LD_X32(r, ta) \
    asm volatile( \
        "tcgen05.ld.sync.aligned.32x32b.x32.b32 " \
        "{%0,%1,%2,%3,%4,%5,%6,%7,%8,%9,%10,%11,%12,%13,%14,%15," \
        "%16,%17,%18,%19,%20,%21,%22,%23,%24,%25,%26,%27,%28,%29,%30,%31}, [%32];" \
        : "=r"((r)[0]),"=r"((r)[1]),"=r"((r)[2]),"=r"((r)[3]), \
          "=r"((r)[4]),"=r"((r)[5]),"=r"((r)[6]),"=r"((r)[7]), \
          "=r"((r)[8]),"=r"((r)[9]),"=r"((r)[10]),"=r"((r)[11]), \
          "=r"((r)[12]),"=r"((r)[13]),"=r"((r)[14]),"=r"((r)[15]), \
          "=r"((r)[16]),"=r"((r)[17]),"=r"((r)[18]),"=r"((r)[19]), \
          "=r"((r)[20]),"=r"((r)[21]),"=r"((r)[22]),"=r"((r)[23]), \
          "=r"((r)[24]),"=r"((r)[25]),"=r"((r)[26]),"=r"((r)[27]), \
          "=r"((r)[28]),"=r"((r)[29]),"=r"((r)[30]),"=r"((r)[31]) \
        : "r"(ta))
#endif  // HAS_TC

// ---------------------------------------------------------------------------
// Kernel 2a: tcgen05 256x256 triangle GEMM, per-CTA TMA single-thread
// pipeline + fused square-sum epilogue + finalize
// ---------------------------------------------------------------------------
__global__ __launch_bounds__(256, 1)
void gemm_tc(float* out, const __grid_constant__ CUtensorMap tmap) {
#if HAS_TC
    extern __shared__ __align__(16) char smem[];
    uint32_t smem_base = (smem_u32(smem) + 1023u) & ~1023u;
    int tid = threadIdx.x;
    int wid = tid >> 5;
    int lid = tid & 31;

    // block -> (ti, tj) over triangle tj >= ti of 16x16 256-tiles
    int b = blockIdx.x;
    int ti = 0;
    while (b >= (NT - ti)) { b -= (NT - ti); ti++; }
    int tj = ti + b;

    // header: [0] tmem ptr; full[3]@8; mma[3]@32; final@56
    uint32_t full0 = smem_base + 8, mma0 = smem_base + 32, finmb = smem_base + 56;

    if (wid == 0) TC_ALLOC(smem_base, 512);
    if (tid == 0) {
#pragma unroll
        for (int s = 0; s < NSTAGE; s++) {
            MBAR_INIT(full0 + 8 * s, 1);
            MBAR_INIT(mma0 + 8 * s, 1);
        }
        MBAR_INIT(finmb, 1);
    }
    __syncthreads();
    uint32_t tmem;
    asm volatile("ld.shared.b32 %0, [%1];" : "=r"(tmem) : "r"(smem_base));

    uint32_t stA[NSTAGE], stB[NSTAGE];
#pragma unroll
    for (int s = 0; s < NSTAGE; s++) {
        stA[s] = smem_base + SMEM_HDR + s * STAGE_BYTES;
        stB[s] = stA[s] + A_STAGE_BYTES;
    }

    const CUtensorMap* tm = &tmap;
    int rowA = ti * BM;
    int rowB = tj * BN;

    if (tid == 0) {
        // prologue: chunks 0..NSTAGE-2 in flight
#pragma unroll
        for (int pc = 0; pc < NSTAGE - 1; pc++) {
            MBAR_EXPECT_TX(full0 + 8 * pc, STAGE_BYTES);
            TMA2D(stA[pc], tm, pc * KC, rowA, full0 + 8 * pc);
            TMA2D(stB[pc], tm, pc * KC, rowB, full0 + 8 * pc);
        }

        for (int c = 0; c < NCHUNK; c++) {
            int st = c % NSTAGE;
            MBAR_WAIT(full0 + 8 * st, (c / NSTAGE) & 1);

            uint64_t ad  = make_desc(stA[st]);
            uint64_t ad2 = make_desc(stA[st] + 16384);
            uint64_t bd  = make_desc(stB[st]);
            uint32_t idesc = (c >= NEGCHUNK) ? MMA_IDESC_NEGB : MMA_IDESC;
#pragma unroll
            for (int k = 0; k < 4; k++) {
                uint32_t e = (c > 0 || k > 0) ? 1u : 0u;
                mma_f16_ss(tmem,       ad  + 2 * k, bd + 2 * k, idesc, e);
                mma_f16_ss(tmem + 256, ad2 + 2 * k, bd + 2 * k, idesc, e);
            }
            if (c == NCHUNK - 1) TC_COMMIT(finmb);
            else                 TC_COMMIT(mma0 + 8 * st);

            int pre = c + NSTAGE - 1;
            if (pre < NCHUNK) {
                int sp = pre % NSTAGE;
                if (pre >= NSTAGE)   // stage free once chunk pre-3's MMA retired
                    MBAR_WAIT(mma0 + 8 * sp, ((pre / NSTAGE) - 1) & 1);
                MBAR_EXPECT_TX(full0 + 8 * sp, STAGE_BYTES);
                TMA2D(stA[sp], tm, pre * KC, rowA, full0 + 8 * sp);
                TMA2D(stB[sp], tm, pre * KC, rowB, full0 + 8 * sp);
            }
        }
    }

    // all threads: one-shot final MMA barrier (unambiguous phase 0)
    MBAR_WAIT(finmb, 0);
    TC_FENCE_AFTER();

    // epilogue: warps 0-3 -> rows 0..127, warps 4-7 -> rows 128..255
    __shared__ float red[8];
    {
        int half = wid >> 2;
        uint32_t dbase = tmem + half * 256;
        int i = ti * BM + half * 128 + (wid & 3) * 32 + lid;
        float lsum = 0.f;
#pragma unroll
        for (int cb = 0; cb < 8; cb++) {
            uint32_t r[32];
            TC_LD_X32(r, dbase + cb * 32);
            TC_WAIT_LD();
            int jb = tj * BN + cb * 32;
#pragma unroll
            for (int cc = 0; cc < 32; cc++) {
                if (jb + cc > i) {
                    float f = __uint_as_float(r[cc]);
                    lsum += f * f;
                }
            }
        }
        lsum *= 2.f;
#pragma unroll
        for (int o = 16; o; o >>= 1) lsum += __shfl_xor_sync(0xffffffffu, lsum, o);
        if (lid == 0) red[wid] = lsum;
    }
    TC_FENCE_BEFORE();
    __syncthreads();
    if (tid == 0) {
        double s = 0.0;
#pragma unroll
        for (int w = 0; w < 8; w++) s += (double)red[w];
        atomicAdd(&g_acc, s);
#pragma unroll
        for (int st = 0; st < NSTAGE; st++) {
            MBAR_INVAL(full0 + 8 * st);
            MBAR_INVAL(mma0 + 8 * st);
        }
        MBAR_INVAL(finmb);
    }
    __syncthreads();
    if (wid == 0) {
        TC_RELINQ();
        TC_DEALLOC(tmem, 512);
    }
    block_finalize(tid, out, NTILES_TC);
#endif  // HAS_TC
}

// ---------------------------------------------------------------------------
// FFMA2 helpers + fallback GEMM (base-target builds only)
// ---------------------------------------------------------------------------
__device__ __forceinline__ unsigned long long pack_dup(float a) {
    unsigned long long r;
    asm("mov.b64 %0, {%1, %1};" : "=l"(r) : "f"(a));
    return r;
}
__device__ __forceinline__ void ffma2(unsigned long long& d,
                                      unsigned long long a,
                                      unsigned long long b) {
    asm("fma.rn.f32x2 %0, %1, %2, %0;" : "+l"(d) : "l"(a), "l"(b));
}

__global__ __launch_bounds__(256) void gemm_ffma(float* out) {
#if !HAS_TC
    int b = blockIdx.x;
    int ti = 0;
    while (b >= (32 - ti)) { b -= (32 - ti); ti++; }
    int tj = ti + b;

    __shared__ __align__(16) float As[FBK][LDSS];
    __shared__ __align__(16) float Bs[FBK][LDSS];
    __shared__ float red[8];

    int tid = threadIdx.x;
    int tx = tid & 15;
    int ty = tid >> 4;

    const __nv_bfloat16* Abase = g_P + (size_t)ti * FBM * KTOT;
    const __nv_bfloat16* Bbase = g_P + (size_t)tj * FBM * KTOT;

    int l_row = tid >> 1;
    int l_k8  = (tid & 1) * 8;

    unsigned long long acc[8][4];
#pragma unroll
    for (int r = 0; r < 8; r++)
#pragma unroll
        for (int c = 0; c < 4; c++) acc[r][c] = 0ull;

    uint4 ra = *reinterpret_cast<const uint4*>(
        reinterpret_cast<const char*>(Abase) + (size_t)(l_row * KTOT + l_k8) * 2);
    uint4 rb = *reinterpret_cast<const uint4*>(
        reinterpret_cast<const char*>(Bbase) + (size_t)(l_row * KTOT + l_k8) * 2);

    for (int kb = 0; kb < KTOT; kb += FBK) {
        float sgn = (kb >= DDIM) ? -1.0f : 1.0f;
        union { uint4 u; __nv_bfloat162 h[4]; } wa, wb;
        wa.u = ra; wb.u = rb;
#pragma unroll
        for (int j = 0; j < 4; j++) {
            float2 fa = __bfloat1622float2(wa.h[j]);
            float2 fb = __bfloat1622float2(wb.h[j]);
            As[l_k8 + 2 * j][l_row]     = fa.x;
            As[l_k8 + 2 * j + 1][l_row] = fa.y;
            Bs[l_k8 + 2 * j][l_row]     = sgn * fb.x;
            Bs[l_k8 + 2 * j + 1][l_row] = sgn * fb.y;
        }
        __syncthreads();

        if (kb + FBK < KTOT) {
            int kn = kb + FBK;
            ra = *reinterpret_cast<const uint4*>(
                reinterpret_cast<const char*>(Abase) + (size_t)(l_row * KTOT + kn + l_k8) * 2);
            rb = *reinterpret_cast<const uint4*>(
                reinterpret_cast<const char*>(Bbase) + (size_t)(l_row * KTOT + kn + l_k8) * 2);
        }

#pragma unroll
        for (int kk = 0; kk < FBK; kk++) {
            float a[8];
            *reinterpret_cast<float4*>(&a[0]) =
                *reinterpret_cast<const float4*>(&As[kk][ty * 8]);
            *reinterpret_cast<float4*>(&a[4]) =
                *reinterpret_cast<const float4*>(&As[kk][ty * 8 + 4]);
            union { float4 v[2]; unsigned long long u[4]; } bu;
            bu.v[0] = *reinterpret_cast<const float4*>(&Bs[kk][tx * 8]);
            bu.v[1] = *reinterpret_cast<const float4*>(&Bs[kk][tx * 8 + 4]);
#pragma unroll
            for (int r = 0; r < 8; r++) {
                unsigned long long aa = pack_dup(a[r]);
#pragma unroll
                for (int c = 0; c < 4; c++) ffma2(acc[r][c], aa, bu.u[c]);
            }
        }
        __syncthreads();
    }

    int gi0 = ti * FBM + ty * 8;
    int gj0 = tj * FBM + tx * 8;
    float lsum = 0.f;
#pragma unroll
    for (int r = 0; r < 8; r++) {
        int i = gi0 + r;
#pragma unroll
        for (int c = 0; c < 4; c++) {
            union { unsigned long long u; float f[2]; } w;
            w.u = acc[r][c];
            int j0 = gj0 + 2 * c;
            if (j0 > i)     lsum += w.f[0] * w.f[0];
            if (j0 + 1 > i) lsum += w.f[1] * w.f[1];
        }
    }
    lsum *= 2.f;

#pragma unroll
    for (int o = 16; o; o >>= 1) lsum += __shfl_xor_sync(0xffffffffu, lsum, o);
    if ((tid & 31) == 0) red[tid >> 5] = lsum;
    __syncthreads();
    if (tid == 0) {
        double s = 0.0;
#pragma unroll
        for (int w = 0; w < 8; w++) s += (double)red[w];
        atomicAdd(&g_acc, s);
    }
    __syncthreads();
    block_finalize(tid, out, NTILES_FF);
#endif  // !HAS_TC
}

// ---------------------------------------------------------------------------
// Host
// ---------------------------------------------------------------------------
typedef CUresult (*PFN_tmapEncode)(
    CUtensorMap*, CUtensorMapDataType, cuuint32_t, void*,
    const cuuint64_t*, const cuuint64_t*, const cuuint32_t*, const cuuint32_t*,
    CUtensorMapInterleave, CUtensorMapSwizzle, CUtensorMapL2promotion,
    CUtensorMapFloatOOBfill);

static CUtensorMap s_tmap;

extern "C" void kernel_launch(void* const* d_in, const int* in_sizes, int n_in,
                              void* d_out, int out_size) {
    const float* fq = (const float*)d_in[0];
    const float* fk = (const float*)d_in[1];
    (void)in_sizes; (void)n_in; (void)out_size;

    cudaFuncSetAttribute(gemm_tc,
                         cudaFuncAttributeMaxDynamicSharedMemorySize, SMEM_DYN);

    // TMA descriptor for g_P (bf16 [NROWS x KTOT], box 64x256, SW128)
    void* pbase = nullptr;
    cudaGetSymbolAddress(&pbase, g_P);
    void* fn = nullptr;
    cudaDriverEntryPointQueryResult qr;
    cudaGetDriverEntryPointByVersion("cuTensorMapEncodeTiled", &fn, 12000,
                                     cudaEnableDefault, &qr);
    if (fn && pbase) {
        cuuint64_t dims[2]    = {(cuuint64_t)KTOT, (cuuint64_t)NROWS};
        cuuint64_t strides[1] = {(cuuint64_t)KTOT * 2};
        cuuint32_t box[2]     = {KC, 256};
        cuuint32_t es[2]      = {1, 1};
        ((PFN_tmapEncode)fn)(&s_tmap, CU_TENSOR_MAP_DATA_TYPE_BFLOAT16, 2, pbase,
                             dims, strides, box, es,
                             CU_TENSOR_MAP_INTERLEAVE_NONE,
                             CU_TENSOR_MAP_SWIZZLE_128B,
                             CU_TENSOR_MAP_L2_PROMOTION_L2_128B,
                             CU_TENSOR_MAP_FLOAT_OOB_FILL_NONE);
    }

    norm_kernel<<<NROWS / 2, 256>>>(fq, fk);                // 4 rows/block
    gemm_tc<<<NTILES_TC, 256, SMEM_DYN>>>((float*)d_out, s_tmap);
    gemm_ffma<<<NTILES_FF, 256>>>((float*)d_out);
}

// round 9
// speedup vs baseline: 1.2057x; 1.0528x over previous
#include <cuda.h>
#include <cuda_runtime.h>
#include <cuda_bf16.h>
#include <cstdint>

// loss = mean_{i!=j} (cos(q_i,q_j) - cos(k_i,k_j))^2
// Sq_ij - Sk_ij = [u_i,v_i].[u_j,-v_j]  =>  C = P @ P^T with b_negate on the
// v-half K-chunks (idesc bit 14). tcgen05 path: per-CTA TMA single-thread
// pipeline (no block syncs, no clusters). Epilogue square-sums the strict
// upper triangle (x2); finalize fused into the last CTA via arrival counter.
// Host dispatches tc vs ffma path on runtime compute capability.

#if defined(__CUDA_ARCH_FEAT_SM100_ALL) || defined(__CUDA_ARCH_FEAT_SM103_ALL) || \
    (defined(__CUDA_ARCH_SPECIFIC__) && (__CUDA_ARCH_SPECIFIC__ >= 1000) && (__CUDA_ARCH_SPECIFIC__ < 1100))
#define HAS_TC 1
#else
#define HAS_TC 0
#endif

#define NROWS 4096
#define DDIM  1024
#define KTOT  2048

// ---- tcgen05 tile config: 256x256 tile per CTA (2 x M128/N256 MMA) ----
#define BM 256
#define BN 256
#define KC 64                       // bf16 elems per chunk (128 B per row)
#define NCHUNK (KTOT / KC)          // 32
#define NEGCHUNK (DDIM / KC)        // 16
#define NSTAGE 3
#define NT  (NROWS / 256)           // 16
#define NTILES_TC 136               // triangle tj >= ti of 16x16

#define A_STAGE_BYTES (BM * 128)    // 32768
#define B_STAGE_BYTES (BN * 128)    // 32768
#define STAGE_BYTES   (A_STAGE_BYTES + B_STAGE_BYTES)   // 65536
#define SMEM_HDR      1024
#define SMEM_DYN      (1024 + SMEM_HDR + NSTAGE * STAGE_BYTES)

// idesc: F32 acc, BF16 a/b, N=256, M=128, K-major; bit14 = b_negate
#define MMA_IDESC ((1u<<4) | (1u<<7) | (1u<<10) | ((256u/8u)<<17) | ((128u/16u)<<24))
#define MMA_IDESC_NEGB (MMA_IDESC | (1u<<14))

// ---- FFMA fallback tile config ----
#define FBM 128
#define FBK 16
#define LDSS 132
#define NTILES_FF 528

__device__ __nv_bfloat16 g_P[(size_t)NROWS * KTOT];  // [u, v] (unit rows)
__device__ double g_acc;
__device__ unsigned int g_count;

// ---------------------------------------------------------------------------
// Arch-neutral helpers
// ---------------------------------------------------------------------------
__device__ __forceinline__ uint32_t smem_u32(const void* p) {
    uint32_t a;
    asm("{ .reg .u64 t; cvta.to.shared.u64 t, %1; cvt.u32.u64 %0, t; }"
        : "=r"(a) : "l"(p));
    return a;
}

#define MBAR_INIT(a, n) \
    asm volatile("mbarrier.init.shared.b64 [%0], %1;" :: "r"(a), "r"(n) : "memory")
#define MBAR_INVAL(a) \
    asm volatile("mbarrier.inval.shared.b64 [%0];" :: "r"(a) : "memory")
#define MBAR_EXPECT_TX(a, tx) \
    asm volatile("mbarrier.arrive.expect_tx.shared.b64 _, [%0], %1;" \
                 :: "r"(a), "r"(tx) : "memory")
#define MBAR_WAIT(a, p) do { \
    uint32_t _m = (a); uint32_t _p = (p); uint32_t _d; \
    asm volatile("{\n\t.reg .pred q;\n\t" \
        "mbarrier.try_wait.parity.acquire.cta.shared::cta.b64 q, [%1], %2;\n\t" \
        "selp.b32 %0, 1, 0, q;\n\t}" : "=r"(_d) : "r"(_m), "r"(_p) : "memory"); \
    if (!_d) { \
        asm volatile("{\n\t.reg .pred Q1;\n\tWL_%=:\n\t" \
            "mbarrier.try_wait.parity.acquire.cta.shared::cta.b64 Q1, [%0], %1, 0x989680;\n\t" \
            "@Q1 bra.uni WD_%=;\n\tbra.uni WL_%=;\n\tWD_%=:\n\t}" \
            :: "r"(_m), "r"(_p) : "memory"); \
    } } while (0)

// finalize fused into last CTA
__device__ __forceinline__ void block_finalize(int tid, float* out, unsigned ntiles) {
    if (tid == 0) {
        __threadfence();
        unsigned old = atomicAdd(&g_count, 1u);
        if (old == ntiles - 1) {
            double s = atomicAdd(&g_acc, 0.0);
            out[0] = (float)(s / ((double)NROWS * (double)(NROWS - 1)));
            g_acc = 0.0;
            g_count = 0u;
            __threadfence();
        }
    }
}

// ---------------------------------------------------------------------------
// Kernel 1: normalize rows -> bf16 P=[u,v].
// Warp-per-row: 8 independent coalesced LDG.128 per lane (MLP=8), butterfly
// reduce (all lanes get the sum), 8 x 8B packed stores. No block syncs.
// ---------------------------------------------------------------------------
__global__ __launch_bounds__(256) void norm_kernel(const float* __restrict__ fq,
                                                   const float* __restrict__ fk) {
    int t = threadIdx.x;
    int w = t >> 5;                    // warp in block
    int lane = t & 31;
    int slot = blockIdx.x * 8 + w;     // 0..8191
    int row = slot & (NROWS - 1);
    int which = slot >> 12;            // 0 = q, 1 = k
    const float* src = (which ? fk : fq) + (size_t)row * DDIM;

    // 8 independent, fully coalesced 16B loads per lane
    float4 v[8];
#pragma unroll
    for (int i = 0; i < 8; i++)
        v[i] = reinterpret_cast<const float4*>(src)[lane + 32 * i];

    float ss = 0.f;
#pragma unroll
    for (int i = 0; i < 8; i++)
        ss += v[i].x * v[i].x + v[i].y * v[i].y + v[i].z * v[i].z + v[i].w * v[i].w;
#pragma unroll
    for (int o = 16; o; o >>= 1) ss += __shfl_xor_sync(0xffffffffu, ss, o);

    float inv = rsqrtf(ss);            // every lane has the full sum

    size_t base = (size_t)row * KTOT + (size_t)which * DDIM;
#pragma unroll
    for (int i = 0; i < 8; i++) {
        union { uint2 u; __nv_bfloat162 b[2]; } wq;
        wq.b[0] = __floats2bfloat162_rn(v[i].x * inv, v[i].y * inv);
        wq.b[1] = __floats2bfloat162_rn(v[i].z * inv, v[i].w * inv);
        *reinterpret_cast<uint2*>(&g_P[base + (size_t)(lane + 32 * i) * 4]) = wq.u;
    }

    if (blockIdx.x == 0 && t == 0) g_acc = 0.0;
}

// ---------------------------------------------------------------------------
// tcgen05-only helpers
// ---------------------------------------------------------------------------
#if HAS_TC
#define TC_ALLOC(sa, n) \
    asm volatile("tcgen05.alloc.cta_group::1.sync.aligned.shared::cta.b32 [%0], %1;" \
                 :: "r"(sa), "r"(n) : "memory")
#define TC_RELINQ() \
    asm volatile("tcgen05.relinquish_alloc_permit.cta_group::1.sync.aligned;")
#define TC_DEALLOC(t, n) \
    asm volatile("tcgen05.dealloc.cta_group::1.sync.aligned.b32 %0, %1;" :: "r"(t), "r"(n))
#define TC_COMMIT(mb) \
    asm volatile("tcgen05.commit.cta_group::1.mbarrier::arrive::one.shared::cluster.b64 [%0];" \
                 :: "r"(mb) : "memory")
#define TC_FENCE_AFTER() asm volatile("tcgen05.fence::after_thread_sync;" ::: "memory")
#define TC_FENCE_BEFORE() asm volatile("tcgen05.fence::before_thread_sync;" ::: "memory")
#define TC_WAIT_LD() asm volatile("tcgen05.wait::ld.sync.aligned;" ::: "memory")

// 2D TMA load into this CTA's smem
#define TMA2D(smem, tmap_p, x, y, mbar) \
    asm volatile( \
        "cp.async.bulk.tensor.2d.shared::cta.global.tile.mbarrier::complete_tx::bytes " \
        "[%0], [%1, {%2, %3}], [%4];" \
        :: "r"(smem), "l"(tmap_p), "r"(x), "r"(y), "r"(mbar) : "memory")

// SW128 K-major SMEM descriptor (LBO=1, SBO=64, version=1)
__device__ __forceinline__ uint64_t make_desc(uint32_t addr) {
    return (uint64_t(2) << 61) | (uint64_t(1) << 46) | (uint64_t(64) << 32)
         | (uint64_t(1) << 16) | ((uint64_t)(addr >> 4) & 0x3FFF);
}

__device__ __forceinline__ void mma_f16_ss(uint32_t d, uint64_t a, uint64_t b,
                                           uint32_t idesc, uint32_t enable) {
    asm volatile(
        "{\n\t.reg .pred p;\n\tsetp.ne.u32 p, %5, 0;\n\t"
        "tcgen05.mma.cta_group::1.kind::f16 [%0], %1, %2, %3, {%4,%4,%4,%4}, p;\n\t}"
        :: "r"(d), "l"(a), "l"(b), "r"(idesc), "r"(0u), "r"(enable) : "memory");
}

#define TC_LD_X32(r, ta) \
    asm volatile( \
        "tcgen05.ld.sync.aligned.32x32b.x32.b32 " \
        "{%0,%1,%2,%3,%4,%5,%6,%7,%8,%9,%10,%11,%12,%13,%14,%15," \
        "%16,%17,%18,%19,%20,%21,%22,%23,%24,%25,%26,%27,%28,%29,%30,%31}, [%32];" \
        : "=r"((r)[0]),"=r"((r)[1]),"=r"((r)[2]),"=r"((r)[3]), \
          "=r"((r)[4]),"=r"((r)[5]),"=r"((r)[6]),"=r"((r)[7]), \
          "=r"((r)[8]),"=r"((r)[9]),"=r"((r)[10]),"=r"((r)[11]), \
          "=r"((r)[12]),"=r"((r)[13]),"=r"((r)[14]),"=r"((r)[15]), \
          "=r"((r)[16]),"=r"((r)[17]),"=r"((r)[18]),"=r"((r)[19]), \
          "=r"((r)[20]),"=r"((r)[21]),"=r"((r)[22]),"=r"((r)[23]), \
          "=r"((r)[24]),"=r"((r)[25]),"=r"((r)[26]),"=r"((r)[27]), \
          "=r"((r)[28]),"=r"((r)[29]),"=r"((r)[30]),"=r"((r)[31]) \
        : "r"(ta))
#endif  // HAS_TC

// ---------------------------------------------------------------------------
// Kernel 2a: tcgen05 256x256 triangle GEMM, per-CTA TMA single-thread
// pipeline + fused square-sum epilogue + finalize
// ---------------------------------------------------------------------------
__global__ __launch_bounds__(256, 1)
void gemm_tc(float* out, const __grid_constant__ CUtensorMap tmap) {
#if HAS_TC
    extern __shared__ __align__(16) char smem[];
    uint32_t smem_base = (smem_u32(smem) + 1023u) & ~1023u;
    int tid = threadIdx.x;
    int wid = tid >> 5;
    int lid = tid & 31;

    // block -> (ti, tj) over triangle tj >= ti of 16x16 256-tiles
    int b = blockIdx.x;
    int ti = 0;
    while (b >= (NT - ti)) { b -= (NT - ti); ti++; }
    int tj = ti + b;

    // header: [0] tmem ptr; full[3]@8; mma[3]@32; final@56
    uint32_t full0 = smem_base + 8, mma0 = smem_base + 32, finmb = smem_base + 56;

    if (wid == 0) TC_ALLOC(smem_base, 512);
    if (tid == 0) {
#pragma unroll
        for (int s = 0; s < NSTAGE; s++) {
            MBAR_INIT(full0 + 8 * s, 1);
            MBAR_INIT(mma0 + 8 * s, 1);
        }
        MBAR_INIT(finmb, 1);
    }
    __syncthreads();
    uint32_t tmem;
    asm volatile("ld.shared.b32 %0, [%1];" : "=r"(tmem) : "r"(smem_base));

    uint32_t stA[NSTAGE], stB[NSTAGE];
#pragma unroll
    for (int s = 0; s < NSTAGE; s++) {
        stA[s] = smem_base + SMEM_HDR + s * STAGE_BYTES;
        stB[s] = stA[s] + A_STAGE_BYTES;
    }

    const CUtensorMap* tm = &tmap;
    int rowA = ti * BM;
    int rowB = tj * BN;

    if (tid == 0) {
        // prologue: chunks 0..NSTAGE-2 in flight
#pragma unroll
        for (int pc = 0; pc < NSTAGE - 1; pc++) {
            MBAR_EXPECT_TX(full0 + 8 * pc, STAGE_BYTES);
            TMA2D(stA[pc], tm, pc * KC, rowA, full0 + 8 * pc);
            TMA2D(stB[pc], tm, pc * KC, rowB, full0 + 8 * pc);
        }

        for (int c = 0; c < NCHUNK; c++) {
            int st = c % NSTAGE;
            MBAR_WAIT(full0 + 8 * st, (c / NSTAGE) & 1);

            uint64_t ad  = make_desc(stA[st]);
            uint64_t ad2 = make_desc(stA[st] + 16384);
            uint64_t bd  = make_desc(stB[st]);
            uint32_t idesc = (c >= NEGCHUNK) ? MMA_IDESC_NEGB : MMA_IDESC;
#pragma unroll
            for (int k = 0; k < 4; k++) {
                uint32_t e = (c > 0 || k > 0) ? 1u : 0u;
                mma_f16_ss(tmem,       ad  + 2 * k, bd + 2 * k, idesc, e);
                mma_f16_ss(tmem + 256, ad2 + 2 * k, bd + 2 * k, idesc, e);
            }
            if (c == NCHUNK - 1) TC_COMMIT(finmb);
            else                 TC_COMMIT(mma0 + 8 * st);

            int pre = c + NSTAGE - 1;
            if (pre < NCHUNK) {
                int sp = pre % NSTAGE;
                if (pre >= NSTAGE)   // stage free once chunk pre-3's MMA retired
                    MBAR_WAIT(mma0 + 8 * sp, ((pre / NSTAGE) - 1) & 1);
                MBAR_EXPECT_TX(full0 + 8 * sp, STAGE_BYTES);
                TMA2D(stA[sp], tm, pre * KC, rowA, full0 + 8 * sp);
                TMA2D(stB[sp], tm, pre * KC, rowB, full0 + 8 * sp);
            }
        }
    }

    // all threads: one-shot final MMA barrier (unambiguous phase 0)
    MBAR_WAIT(finmb, 0);
    TC_FENCE_AFTER();

    // epilogue: warps 0-3 -> rows 0..127, warps 4-7 -> rows 128..255
    __shared__ float red[8];
    {
        int half = wid >> 2;
        uint32_t dbase = tmem + half * 256;
        int i = ti * BM + half * 128 + (wid & 3) * 32 + lid;
        float lsum = 0.f;
#pragma unroll
        for (int cb = 0; cb < 8; cb++) {
            uint32_t r[32];
            TC_LD_X32(r, dbase + cb * 32);
            TC_WAIT_LD();
            int jb = tj * BN + cb * 32;
#pragma unroll
            for (int cc = 0; cc < 32; cc++) {
                if (jb + cc > i) {
                    float f = __uint_as_float(r[cc]);
                    lsum += f * f;
                }
            }
        }
        lsum *= 2.f;
#pragma unroll
        for (int o = 16; o; o >>= 1) lsum += __shfl_xor_sync(0xffffffffu, lsum, o);
        if (lid == 0) red[wid] = lsum;
    }
    TC_FENCE_BEFORE();
    __syncthreads();
    if (tid == 0) {
        double s = 0.0;
#pragma unroll
        for (int w = 0; w < 8; w++) s += (double)red[w];
        atomicAdd(&g_acc, s);
#pragma unroll
        for (int st = 0; st < NSTAGE; st++) {
            MBAR_INVAL(full0 + 8 * st);
            MBAR_INVAL(mma0 + 8 * st);
        }
        MBAR_INVAL(finmb);
    }
    __syncthreads();
    if (wid == 0) {
        TC_RELINQ();
        TC_DEALLOC(tmem, 512);
    }
    block_finalize(tid, out, NTILES_TC);
#endif  // HAS_TC
}

// ---------------------------------------------------------------------------
// FFMA2 helpers + fallback GEMM (base-target builds only)
// ---------------------------------------------------------------------------
__device__ __forceinline__ unsigned long long pack_dup(float a) {
    unsigned long long r;
    asm("mov.b64 %0, {%1, %1};" : "=l"(r) : "f"(a));
    return r;
}
__device__ __forceinline__ void ffma2(unsigned long long& d,
                                      unsigned long long a,
                                      unsigned long long b) {
    asm("fma.rn.f32x2 %0, %1, %2, %0;" : "+l"(d) : "l"(a), "l"(b));
}

__global__ __launch_bounds__(256) void gemm_ffma(float* out) {
#if !HAS_TC
    int b = blockIdx.x;
    int ti = 0;
    while (b >= (32 - ti)) { b -= (32 - ti); ti++; }
    int tj = ti + b;

    __shared__ __align__(16) float As[FBK][LDSS];
    __shared__ __align__(16) float Bs[FBK][LDSS];
    __shared__ float red[8];

    int tid = threadIdx.x;
    int tx = tid & 15;
    int ty = tid >> 4;

    const __nv_bfloat16* Abase = g_P + (size_t)ti * FBM * KTOT;
    const __nv_bfloat16* Bbase = g_P + (size_t)tj * FBM * KTOT;

    int l_row = tid >> 1;
    int l_k8  = (tid & 1) * 8;

    unsigned long long acc[8][4];
#pragma unroll
    for (int r = 0; r < 8; r++)
#pragma unroll
        for (int c = 0; c < 4; c++) acc[r][c] = 0ull;

    uint4 ra = *reinterpret_cast<const uint4*>(
        reinterpret_cast<const char*>(Abase) + (size_t)(l_row * KTOT + l_k8) * 2);
    uint4 rb = *reinterpret_cast<const uint4*>(
        reinterpret_cast<const char*>(Bbase) + (size_t)(l_row * KTOT + l_k8) * 2);

    for (int kb = 0; kb < KTOT; kb += FBK) {
        float sgn = (kb >= DDIM) ? -1.0f : 1.0f;
        union { uint4 u; __nv_bfloat162 h[4]; } wa, wb;
        wa.u = ra; wb.u = rb;
#pragma unroll
        for (int j = 0; j < 4; j++) {
            float2 fa = __bfloat1622float2(wa.h[j]);
            float2 fb = __bfloat1622float2(wb.h[j]);
            As[l_k8 + 2 * j][l_row]     = fa.x;
            As[l_k8 + 2 * j + 1][l_row] = fa.y;
            Bs[l_k8 + 2 * j][l_row]     = sgn * fb.x;
            Bs[l_k8 + 2 * j + 1][l_row] = sgn * fb.y;
        }
        __syncthreads();

        if (kb + FBK < KTOT) {
            int kn = kb + FBK;
            ra = *reinterpret_cast<const uint4*>(
                reinterpret_cast<const char*>(Abase) + (size_t)(l_row * KTOT + kn + l_k8) * 2);
            rb = *reinterpret_cast<const uint4*>(
                reinterpret_cast<const char*>(Bbase) + (size_t)(l_row * KTOT + kn + l_k8) * 2);
        }

#pragma unroll
        for (int kk = 0; kk < FBK; kk++) {
            float a[8];
            *reinterpret_cast<float4*>(&a[0]) =
                *reinterpret_cast<const float4*>(&As[kk][ty * 8]);
            *reinterpret_cast<float4*>(&a[4]) =
                *reinterpret_cast<const float4*>(&As[kk][ty * 8 + 4]);
            union { float4 v[2]; unsigned long long u[4]; } bu;
            bu.v[0] = *reinterpret_cast<const float4*>(&Bs[kk][tx * 8]);
            bu.v[1] = *reinterpret_cast<const float4*>(&Bs[kk][tx * 8 + 4]);
#pragma unroll
            for (int r = 0; r < 8; r++) {
                unsigned long long aa = pack_dup(a[r]);
#pragma unroll
                for (int c = 0; c < 4; c++) ffma2(acc[r][c], aa, bu.u[c]);
            }
        }
        __syncthreads();
    }

    int gi0 = ti * FBM + ty * 8;
    int gj0 = tj * FBM + tx * 8;
    float lsum = 0.f;
#pragma unroll
    for (int r = 0; r < 8; r++) {
        int i = gi0 + r;
#pragma unroll
        for (int c = 0; c < 4; c++) {
            union { unsigned long long u; float f[2]; } w;
            w.u = acc[r][c];
            int j0 = gj0 + 2 * c;
            if (j0 > i)     lsum += w.f[0] * w.f[0];
            if (j0 + 1 > i) lsum += w.f[1] * w.f[1];
        }
    }
    lsum *= 2.f;

#pragma unroll
    for (int o = 16; o; o >>= 1) lsum += __shfl_xor_sync(0xffffffffu, lsum, o);
    if ((tid & 31) == 0) red[tid >> 5] = lsum;
    __syncthreads();
    if (tid == 0) {
        double s = 0.0;
#pragma unroll
        for (int w = 0; w < 8; w++) s += (double)red[w];
        atomicAdd(&g_acc, s);
    }
    __syncthreads();
    block_finalize(tid, out, NTILES_FF);
#endif  // !HAS_TC
}

// ---------------------------------------------------------------------------
// Host
// ---------------------------------------------------------------------------
typedef CUresult (*PFN_tmapEncode)(
    CUtensorMap*, CUtensorMapDataType, cuuint32_t, void*,
    const cuuint64_t*, const cuuint64_t*, const cuuint32_t*, const cuuint32_t*,
    CUtensorMapInterleave, CUtensorMapSwizzle, CUtensorMapL2promotion,
    CUtensorMapFloatOOBfill);

static CUtensorMap s_tmap;

extern "C" void kernel_launch(void* const* d_in, const int* in_sizes, int n_in,
                              void* d_out, int out_size) {
    const float* fq = (const float*)d_in[0];
    const float* fk = (const float*)d_in[1];
    (void)in_sizes; (void)n_in; (void)out_size;

    // runtime arch dispatch: sm_10x -> tcgen05 path, else FFMA fallback
    int dev = 0, cc_major = 0;
    cudaGetDevice(&dev);
    cudaDeviceGetAttribute(&cc_major, cudaDevAttrComputeCapabilityMajor, dev);
    bool use_tc = (cc_major == 10);

    if (use_tc) {
        cudaFuncSetAttribute(gemm_tc,
                             cudaFuncAttributeMaxDynamicSharedMemorySize, SMEM_DYN);
        // TMA descriptor for g_P (bf16 [NROWS x KTOT], box 64x256, SW128)
        void* pbase = nullptr;
        cudaGetSymbolAddress(&pbase, g_P);
        void* fn = nullptr;
        cudaDriverEntryPointQueryResult qr;
        cudaGetDriverEntryPointByVersion("cuTensorMapEncodeTiled", &fn, 12000,
                                         cudaEnableDefault, &qr);
        if (fn && pbase) {
            cuuint64_t dims[2]    = {(cuuint64_t)KTOT, (cuuint64_t)NROWS};
            cuuint64_t strides[1] = {(cuuint64_t)KTOT * 2};
            cuuint32_t box[2]     = {KC, 256};
            cuuint32_t es[2]      = {1, 1};
            ((PFN_tmapEncode)fn)(&s_tmap, CU_TENSOR_MAP_DATA_TYPE_BFLOAT16, 2, pbase,
                                 dims, strides, box, es,
                                 CU_TENSOR_MAP_INTERLEAVE_NONE,
                                 CU_TENSOR_MAP_SWIZZLE_128B,
                                 CU_TENSOR_MAP_L2_PROMOTION_L2_128B,
                                 CU_TENSOR_MAP_FLOAT_OOB_FILL_NONE);
        }
    }

    norm_kernel<<<NROWS / 4, 256>>>(fq, fk);                // warp-per-row
    if (use_tc)
        gemm_tc<<<NTILES_TC, 256, SMEM_DYN>>>((float*)d_out, s_tmap);
    else
        gemm_ffma<<<NTILES_FF, 256>>>((float*)d_out);
}

// round 10
// speedup vs baseline: 1.2962x; 1.0750x over previous
#include <cuda.h>
#include <cuda_runtime.h>
#include <cuda_bf16.h>
#include <cstdint>

// loss = mean_{i!=j} (cos(q_i,q_j) - cos(k_i,k_j))^2
// Sq_ij - Sk_ij = [u_i,v_i].[u_j,-v_j]  =>  C = P @ P^T with b_negate on the
// v-half K-chunks (idesc bit 14). tcgen05 path: per-CTA TMA pipeline with
// warp-specialized producer (TMA, thread 32) / consumer (MMA, thread 0).
// Epilogue square-sums the strict upper triangle (x2); finalize fused into
// the last CTA via arrival counter. Host dispatches on runtime CC.

#if defined(__CUDA_ARCH_FEAT_SM100_ALL) || defined(__CUDA_ARCH_FEAT_SM103_ALL) || \
    (defined(__CUDA_ARCH_SPECIFIC__) && (__CUDA_ARCH_SPECIFIC__ >= 1000) && (__CUDA_ARCH_SPECIFIC__ < 1100))
#define HAS_TC 1
#else
#define HAS_TC 0
#endif

#define NROWS 4096
#define DDIM  1024
#define KTOT  2048

// ---- tcgen05 tile config: 256x256 tile per CTA (2 x M128/N256 MMA) ----
#define BM 256
#define BN 256
#define KC 64                       // bf16 elems per chunk (128 B per row)
#define NCHUNK (KTOT / KC)          // 32
#define NEGCHUNK (DDIM / KC)        // 16
#define NSTAGE 3
#define NT  (NROWS / 256)           // 16
#define NTILES_TC 136               // triangle tj >= ti of 16x16

#define A_STAGE_BYTES (BM * 128)    // 32768
#define B_STAGE_BYTES (BN * 128)    // 32768
#define STAGE_BYTES   (A_STAGE_BYTES + B_STAGE_BYTES)   // 65536
#define SMEM_HDR      1024
#define SMEM_DYN      (1024 + SMEM_HDR + NSTAGE * STAGE_BYTES)

// idesc: F32 acc, BF16 a/b, N=256, M=128, K-major; bit14 = b_negate
#define MMA_IDESC ((1u<<4) | (1u<<7) | (1u<<10) | ((256u/8u)<<17) | ((128u/16u)<<24))
#define MMA_IDESC_NEGB (MMA_IDESC | (1u<<14))

// ---- FFMA fallback tile config ----
#define FBM 128
#define FBK 16
#define LDSS 132
#define NTILES_FF 528

__device__ __nv_bfloat16 g_P[(size_t)NROWS * KTOT];  // [u, v] (unit rows)
__device__ double g_acc;
__device__ unsigned int g_count;

// ---------------------------------------------------------------------------
// Arch-neutral helpers
// ---------------------------------------------------------------------------
__device__ __forceinline__ uint32_t smem_u32(const void* p) {
    uint32_t a;
    asm("{ .reg .u64 t; cvta.to.shared.u64 t, %1; cvt.u32.u64 %0, t; }"
        : "=r"(a) : "l"(p));
    return a;
}

#define MBAR_INIT(a, n) \
    asm volatile("mbarrier.init.shared.b64 [%0], %1;" :: "r"(a), "r"(n) : "memory")
#define MBAR_INVAL(a) \
    asm volatile("mbarrier.inval.shared.b64 [%0];" :: "r"(a) : "memory")
#define MBAR_EXPECT_TX(a, tx) \
    asm volatile("mbarrier.arrive.expect_tx.shared.b64 _, [%0], %1;" \
                 :: "r"(a), "r"(tx) : "memory")
#define MBAR_WAIT(a, p) do { \
    uint32_t _m = (a); uint32_t _p = (p); uint32_t _d; \
    asm volatile("{\n\t.reg .pred q;\n\t" \
        "mbarrier.try_wait.parity.acquire.cta.shared::cta.b64 q, [%1], %2;\n\t" \
        "selp.b32 %0, 1, 0, q;\n\t}" : "=r"(_d) : "r"(_m), "r"(_p) : "memory"); \
    if (!_d) { \
        asm volatile("{\n\t.reg .pred Q1;\n\tWL_%=:\n\t" \
            "mbarrier.try_wait.parity.acquire.cta.shared::cta.b64 Q1, [%0], %1, 0x989680;\n\t" \
            "@Q1 bra.uni WD_%=;\n\tbra.uni WL_%=;\n\tWD_%=:\n\t}" \
            :: "r"(_m), "r"(_p) : "memory"); \
    } } while (0)

// finalize fused into last CTA
__device__ __forceinline__ void block_finalize(int tid, float* out, unsigned ntiles) {
    if (tid == 0) {
        __threadfence();
        unsigned old = atomicAdd(&g_count, 1u);
        if (old == ntiles - 1) {
            double s = atomicAdd(&g_acc, 0.0);
            out[0] = (float)(s / ((double)NROWS * (double)(NROWS - 1)));
            g_acc = 0.0;
            g_count = 0u;
            __threadfence();
        }
    }
}

// ---------------------------------------------------------------------------
// Kernel 1: normalize rows -> bf16 P=[u,v]. Warp-per-row, no block syncs.
// ---------------------------------------------------------------------------
__global__ __launch_bounds__(256) void norm_kernel(const float* __restrict__ fq,
                                                   const float* __restrict__ fk) {
    int t = threadIdx.x;
    int w = t >> 5;
    int lane = t & 31;
    int slot = blockIdx.x * 8 + w;
    int row = slot & (NROWS - 1);
    int which = slot >> 12;
    const float* src = (which ? fk : fq) + (size_t)row * DDIM;

    float4 v[8];
#pragma unroll
    for (int i = 0; i < 8; i++)
        v[i] = reinterpret_cast<const float4*>(src)[lane + 32 * i];

    float ss = 0.f;
#pragma unroll
    for (int i = 0; i < 8; i++)
        ss += v[i].x * v[i].x + v[i].y * v[i].y + v[i].z * v[i].z + v[i].w * v[i].w;
#pragma unroll
    for (int o = 16; o; o >>= 1) ss += __shfl_xor_sync(0xffffffffu, ss, o);

    float inv = rsqrtf(ss);

    size_t base = (size_t)row * KTOT + (size_t)which * DDIM;
#pragma unroll
    for (int i = 0; i < 8; i++) {
        union { uint2 u; __nv_bfloat162 b[2]; } wq;
        wq.b[0] = __floats2bfloat162_rn(v[i].x * inv, v[i].y * inv);
        wq.b[1] = __floats2bfloat162_rn(v[i].z * inv, v[i].w * inv);
        *reinterpret_cast<uint2*>(&g_P[base + (size_t)(lane + 32 * i) * 4]) = wq.u;
    }

    if (blockIdx.x == 0 && t == 0) g_acc = 0.0;
}

// ---------------------------------------------------------------------------
// tcgen05-only helpers
// ---------------------------------------------------------------------------
#if HAS_TC
#define TC_ALLOC(sa, n) \
    asm volatile("tcgen05.alloc.cta_group::1.sync.aligned.shared::cta.b32 [%0], %1;" \
                 :: "r"(sa), "r"(n) : "memory")
#define TC_RELINQ() \
    asm volatile("tcgen05.relinquish_alloc_permit.cta_group::1.sync.aligned;")
#define TC_DEALLOC(t, n) \
    asm volatile("tcgen05.dealloc.cta_group::1.sync.aligned.b32 %0, %1;" :: "r"(t), "r"(n))
#define TC_COMMIT(mb) \
    asm volatile("tcgen05.commit.cta_group::1.mbarrier::arrive::one.shared::cluster.b64 [%0];" \
                 :: "r"(mb) : "memory")
#define TC_FENCE_AFTER() asm volatile("tcgen05.fence::after_thread_sync;" ::: "memory")
#define TC_FENCE_BEFORE() asm volatile("tcgen05.fence::before_thread_sync;" ::: "memory")
#define TC_WAIT_LD() asm volatile("tcgen05.wait::ld.sync.aligned;" ::: "memory")

#define TMA2D(smem, tmap_p, x, y, mbar) \
    asm volatile( \
        "cp.async.bulk.tensor.2d.shared::cta.global.tile.mbarrier::complete_tx::bytes " \
        "[%0], [%1, {%2, %3}], [%4];" \
        :: "r"(smem), "l"(tmap_p), "r"(x), "r"(y), "r"(mbar) : "memory")

// SW128 K-major SMEM descriptor (LBO=1, SBO=64, version=1)
__device__ __forceinline__ uint64_t make_desc(uint32_t addr) {
    return (uint64_t(2) << 61) | (uint64_t(1) << 46) | (uint64_t(64) << 32)
         | (uint64_t(1) << 16) | ((uint64_t)(addr >> 4) & 0x3FFF);
}

__device__ __forceinline__ void mma_f16_ss(uint32_t d, uint64_t a, uint64_t b,
                                           uint32_t idesc, uint32_t enable) {
    asm volatile(
        "{\n\t.reg .pred p;\n\tsetp.ne.u32 p, %5, 0;\n\t"
        "tcgen05.mma.cta_group::1.kind::f16 [%0], %1, %2, %3, {%4,%4,%4,%4}, p;\n\t}"
        :: "r"(d), "l"(a), "l"(b), "r"(idesc), "r"(0u), "r"(enable) : "memory");
}

#define TC_LD_X32(r, ta) \
    asm volatile( \
        "tcgen05.ld.sync.aligned.32x32b.x32.b32 " \
        "{%0,%1,%2,%3,%4,%5,%6,%7,%8,%9,%10,%11,%12,%13,%14,%15," \
        "%16,%17,%18,%19,%20,%21,%22,%23,%24,%25,%26,%27,%28,%29,%30,%31}, [%32];" \
        : "=r"((r)[0]),"=r"((r)[1]),"=r"((r)[2]),"=r"((r)[3]), \
          "=r"((r)[4]),"=r"((r)[5]),"=r"((r)[6]),"=r"((r)[7]), \
          "=r"((r)[8]),"=r"((r)[9]),"=r"((r)[10]),"=r"((r)[11]), \
          "=r"((r)[12]),"=r"((r)[13]),"=r"((r)[14]),"=r"((r)[15]), \
          "=r"((r)[16]),"=r"((r)[17]),"=r"((r)[18]),"=r"((r)[19]), \
          "=r"((r)[20]),"=r"((r)[21]),"=r"((r)[22]),"=r"((r)[23]), \
          "=r"((r)[24]),"=r"((r)[25]),"=r"((r)[26]),"=r"((r)[27]), \
          "=r"((r)[28]),"=r"((r)[29]),"=r"((r)[30]),"=r"((r)[31]) \
        : "r"(ta))
#endif  // HAS_TC

// ---------------------------------------------------------------------------
// Kernel 2a: tcgen05 256x256 triangle GEMM, warp-specialized TMA pipeline
// (thread 32 = producer, thread 0 = consumer) + fused epilogue + finalize
// ---------------------------------------------------------------------------
__global__ __launch_bounds__(256, 1)
void gemm_tc(float* out, const __grid_constant__ CUtensorMap tmap) {
#if HAS_TC
    extern __shared__ __align__(16) char smem[];
    uint32_t smem_base = (smem_u32(smem) + 1023u) & ~1023u;
    int tid = threadIdx.x;
    int wid = tid >> 5;
    int lid = tid & 31;

    // block -> (ti, tj) over triangle tj >= ti of 16x16 256-tiles
    int b = blockIdx.x;
    int ti = 0;
    while (b >= (NT - ti)) { b -= (NT - ti); ti++; }
    int tj = ti + b;

    // header: [0] tmem ptr; full[3]@8; mma[3]@32; final@56
    uint32_t full0 = smem_base + 8, mma0 = smem_base + 32, finmb = smem_base + 56;

    if (wid == 0) TC_ALLOC(smem_base, 512);
    if (tid == 0) {
#pragma unroll
        for (int s = 0; s < NSTAGE; s++) {
            MBAR_INIT(full0 + 8 * s, 1);
            MBAR_INIT(mma0 + 8 * s, 1);
        }
        MBAR_INIT(finmb, 1);
    }
    __syncthreads();
    uint32_t tmem;
    asm volatile("ld.shared.b32 %0, [%1];" : "=r"(tmem) : "r"(smem_base));

    uint32_t stA[NSTAGE], stB[NSTAGE];
#pragma unroll
    for (int s = 0; s < NSTAGE; s++) {
        stA[s] = smem_base + SMEM_HDR + s * STAGE_BYTES;
        stB[s] = stA[s] + A_STAGE_BYTES;
    }

    const CUtensorMap* tm = &tmap;
    int rowA = ti * BM;
    int rowB = tj * BN;

    if (tid == 32) {
        // ---- producer (TMA issue) ----
        for (int pre = 0; pre < NCHUNK; pre++) {
            int sp = pre % NSTAGE;
            if (pre >= NSTAGE)   // stage free once chunk pre-NSTAGE's MMA retired
                MBAR_WAIT(mma0 + 8 * sp, ((pre / NSTAGE) - 1) & 1);
            MBAR_EXPECT_TX(full0 + 8 * sp, STAGE_BYTES);
            TMA2D(stA[sp], tm, pre * KC, rowA, full0 + 8 * sp);
            TMA2D(stB[sp], tm, pre * KC, rowB, full0 + 8 * sp);
        }
    } else if (tid == 0) {
        // ---- consumer (MMA issue) ----
        for (int c = 0; c < NCHUNK; c++) {
            int st = c % NSTAGE;
            MBAR_WAIT(full0 + 8 * st, (c / NSTAGE) & 1);

            uint64_t ad  = make_desc(stA[st]);
            uint64_t ad2 = make_desc(stA[st] + 16384);
            uint64_t bd  = make_desc(stB[st]);
            uint32_t idesc = (c >= NEGCHUNK) ? MMA_IDESC_NEGB : MMA_IDESC;
#pragma unroll
            for (int k = 0; k < 4; k++) {
                uint32_t e = (c > 0 || k > 0) ? 1u : 0u;
                mma_f16_ss(tmem,       ad  + 2 * k, bd + 2 * k, idesc, e);
                mma_f16_ss(tmem + 256, ad2 + 2 * k, bd + 2 * k, idesc, e);
            }
            if (c == NCHUNK - 1) TC_COMMIT(finmb);
            else                 TC_COMMIT(mma0 + 8 * st);
        }
    }

    // all threads: one-shot final MMA barrier (unambiguous phase 0)
    MBAR_WAIT(finmb, 0);
    TC_FENCE_AFTER();

    // epilogue: warps 0-3 -> rows 0..127, warps 4-7 -> rows 128..255
    __shared__ float red[8];
    {
        int half = wid >> 2;
        uint32_t dbase = tmem + half * 256;
        int i = ti * BM + half * 128 + (wid & 3) * 32 + lid;
        float lsum = 0.f;
#pragma unroll
        for (int cb = 0; cb < 8; cb++) {
            uint32_t r[32];
            TC_LD_X32(r, dbase + cb * 32);
            TC_WAIT_LD();
            int jb = tj * BN + cb * 32;
#pragma unroll
            for (int cc = 0; cc < 32; cc++) {
                if (jb + cc > i) {
                    float f = __uint_as_float(r[cc]);
                    lsum += f * f;
                }
            }
        }
        lsum *= 2.f;
#pragma unroll
        for (int o = 16; o; o >>= 1) lsum += __shfl_xor_sync(0xffffffffu, lsum, o);
        if (lid == 0) red[wid] = lsum;
    }
    TC_FENCE_BEFORE();
    __syncthreads();
    if (tid == 0) {
        double s = 0.0;
#pragma unroll
        for (int w = 0; w < 8; w++) s += (double)red[w];
        atomicAdd(&g_acc, s);
#pragma unroll
        for (int st = 0; st < NSTAGE; st++) {
            MBAR_INVAL(full0 + 8 * st);
            MBAR_INVAL(mma0 + 8 * st);
        }
        MBAR_INVAL(finmb);
    }
    __syncthreads();
    if (wid == 0) {
        TC_RELINQ();
        TC_DEALLOC(tmem, 512);
    }
    block_finalize(tid, out, NTILES_TC);
#endif  // HAS_TC
}

// ---------------------------------------------------------------------------
// FFMA2 helpers + fallback GEMM (base-target builds only)
// ---------------------------------------------------------------------------
__device__ __forceinline__ unsigned long long pack_dup(float a) {
    unsigned long long r;
    asm("mov.b64 %0, {%1, %1};" : "=l"(r) : "f"(a));
    return r;
}
__device__ __forceinline__ void ffma2(unsigned long long& d,
                                      unsigned long long a,
                                      unsigned long long b) {
    asm("fma.rn.f32x2 %0, %1, %2, %0;" : "+l"(d) : "l"(a), "l"(b));
}

__global__ __launch_bounds__(256) void gemm_ffma(float* out) {
#if !HAS_TC
    int b = blockIdx.x;
    int ti = 0;
    while (b >= (32 - ti)) { b -= (32 - ti); ti++; }
    int tj = ti + b;

    __shared__ __align__(16) float As[FBK][LDSS];
    __shared__ __align__(16) float Bs[FBK][LDSS];
    __shared__ float red[8];

    int tid = threadIdx.x;
    int tx = tid & 15;
    int ty = tid >> 4;

    const __nv_bfloat16* Abase = g_P + (size_t)ti * FBM * KTOT;
    const __nv_bfloat16* Bbase = g_P + (size_t)tj * FBM * KTOT;

    int l_row = tid >> 1;
    int l_k8  = (tid & 1) * 8;

    unsigned long long acc[8][4];
#pragma unroll
    for (int r = 0; r < 8; r++)
#pragma unroll
        for (int c = 0; c < 4; c++) acc[r][c] = 0ull;

    uint4 ra = *reinterpret_cast<const uint4*>(
        reinterpret_cast<const char*>(Abase) + (size_t)(l_row * KTOT + l_k8) * 2);
    uint4 rb = *reinterpret_cast<const uint4*>(
        reinterpret_cast<const char*>(Bbase) + (size_t)(l_row * KTOT + l_k8) * 2);

    for (int kb = 0; kb < KTOT; kb += FBK) {
        float sgn = (kb >= DDIM) ? -1.0f : 1.0f;
        union { uint4 u; __nv_bfloat162 h[4]; } wa, wb;
        wa.u = ra; wb.u = rb;
#pragma unroll
        for (int j = 0; j < 4; j++) {
            float2 fa = __bfloat1622float2(wa.h[j]);
            float2 fb = __bfloat1622float2(wb.h[j]);
            As[l_k8 + 2 * j][l_row]     = fa.x;
            As[l_k8 + 2 * j + 1][l_row] = fa.y;
            Bs[l_k8 + 2 * j][l_row]     = sgn * fb.x;
            Bs[l_k8 + 2 * j + 1][l_row] = sgn * fb.y;
        }
        __syncthreads();

        if (kb + FBK < KTOT) {
            int kn = kb + FBK;
            ra = *reinterpret_cast<const uint4*>(
                reinterpret_cast<const char*>(Abase) + (size_t)(l_row * KTOT + kn + l_k8) * 2);
            rb = *reinterpret_cast<const uint4*>(
                reinterpret_cast<const char*>(Bbase) + (size_t)(l_row * KTOT + kn + l_k8) * 2);
        }

#pragma unroll
        for (int kk = 0; kk < FBK; kk++) {
            float a[8];
            *reinterpret_cast<float4*>(&a[0]) =
                *reinterpret_cast<const float4*>(&As[kk][ty * 8]);
            *reinterpret_cast<float4*>(&a[4]) =
                *reinterpret_cast<const float4*>(&As[kk][ty * 8 + 4]);
            union { float4 v[2]; unsigned long long u[4]; } bu;
            bu.v[0] = *reinterpret_cast<const float4*>(&Bs[kk][tx * 8]);
            bu.v[1] = *reinterpret_cast<const float4*>(&Bs[kk][tx * 8 + 4]);
#pragma unroll
            for (int r = 0; r < 8; r++) {
                unsigned long long aa = pack_dup(a[r]);
#pragma unroll
                for (int c = 0; c < 4; c++) ffma2(acc[r][c], aa, bu.u[c]);
            }
        }
        __syncthreads();
    }

    int gi0 = ti * FBM + ty * 8;
    int gj0 = tj * FBM + tx * 8;
    float lsum = 0.f;
#pragma unroll
    for (int r = 0; r < 8; r++) {
        int i = gi0 + r;
#pragma unroll
        for (int c = 0; c < 4; c++) {
            union { unsigned long long u; float f[2]; } w;
            w.u = acc[r][c];
            int j0 = gj0 + 2 * c;
            if (j0 > i)     lsum += w.f[0] * w.f[0];
            if (j0 + 1 > i) lsum += w.f[1] * w.f[1];
        }
    }
    lsum *= 2.f;

#pragma unroll
    for (int o = 16; o; o >>= 1) lsum += __shfl_xor_sync(0xffffffffu, lsum, o);
    if ((tid & 31) == 0) red[tid >> 5] = lsum;
    __syncthreads();
    if (tid == 0) {
        double s = 0.0;
#pragma unroll
        for (int w = 0; w < 8; w++) s += (double)red[w];
        atomicAdd(&g_acc, s);
    }
    __syncthreads();
    block_finalize(tid, out, NTILES_FF);
#endif  // !HAS_TC
}

// ---------------------------------------------------------------------------
// Host
// ---------------------------------------------------------------------------
typedef CUresult (*PFN_tmapEncode)(
    CUtensorMap*, CUtensorMapDataType, cuuint32_t, void*,
    const cuuint64_t*, const cuuint64_t*, const cuuint32_t*, const cuuint32_t*,
    CUtensorMapInterleave, CUtensorMapSwizzle, CUtensorMapL2promotion,
    CUtensorMapFloatOOBfill);

static CUtensorMap s_tmap;

extern "C" void kernel_launch(void* const* d_in, const int* in_sizes, int n_in,
                              void* d_out, int out_size) {
    const float* fq = (const float*)d_in[0];
    const float* fk = (const float*)d_in[1];
    (void)in_sizes; (void)n_in; (void)out_size;

    int dev = 0, cc_major = 0;
    cudaGetDevice(&dev);
    cudaDeviceGetAttribute(&cc_major, cudaDevAttrComputeCapabilityMajor, dev);
    bool use_tc = (cc_major == 10);

    if (use_tc) {
        cudaFuncSetAttribute(gemm_tc,
                             cudaFuncAttributeMaxDynamicSharedMemorySize, SMEM_DYN);
        void* pbase = nullptr;
        cudaGetSymbolAddress(&pbase, g_P);
        void* fn = nullptr;
        cudaDriverEntryPointQueryResult qr;
        cudaGetDriverEntryPointByVersion("cuTensorMapEncodeTiled", &fn, 12000,
                                         cudaEnableDefault, &qr);
        if (fn && pbase) {
            cuuint64_t dims[2]    = {(cuuint64_t)KTOT, (cuuint64_t)NROWS};
            cuuint64_t strides[1] = {(cuuint64_t)KTOT * 2};
            cuuint32_t box[2]     = {KC, 256};
            cuuint32_t es[2]      = {1, 1};
            ((PFN_tmapEncode)fn)(&s_tmap, CU_TENSOR_MAP_DATA_TYPE_BFLOAT16, 2, pbase,
                                 dims, strides, box, es,
                                 CU_TENSOR_MAP_INTERLEAVE_NONE,
                                 CU_TENSOR_MAP_SWIZZLE_128B,
                                 CU_TENSOR_MAP_L2_PROMOTION_L2_128B,
                                 CU_TENSOR_MAP_FLOAT_OOB_FILL_NONE);
        }
    }

    norm_kernel<<<NROWS / 4, 256>>>(fq, fk);                // warp-per-row
    if (use_tc)
        gemm_tc<<<NTILES_TC, 256, SMEM_DYN>>>((float*)d_out, s_tmap);
    else
        gemm_ffma<<<NTILES_FF, 256>>>((float*)d_out);
}